// round 14
// baseline (speedup 1.0000x reference)
#include <cuda_runtime.h>

typedef unsigned long long ull;

#define NWARPS 4
// per-warp smem floats (2848):
//  sS  @0    (672  = 4*168)            per-row S
//  sT  @672  (1536 = 2*768, H^T stride 12)
//  swd @2208 (592  = 4*148)  [r][h*36+d]   (sh1 272 floats aliases swd during B tail)
//  sA  @2800 (48   = 4*12)   [r][0..7]=adv, [r][8]=sum(adv)
#define WARP_FLOATS 2848

__device__ __forceinline__ ull pk2(float x, float y) {
    ull r; asm("mov.b64 %0, {%1, %2};" : "=l"(r) : "f"(x), "f"(y)); return r;
}
__device__ __forceinline__ ull dup2(float x) {
    ull r; asm("mov.b64 %0, {%1, %1};" : "=l"(r) : "f"(x)); return r;
}
__device__ __forceinline__ void fma2(ull& d, ull a, ull b) {
    asm("fma.rn.f32x2 %0, %1, %2, %0;" : "+l"(d) : "l"(a), "l"(b));
}
__device__ __forceinline__ ull add2(ull a, ull b) {
    ull r; asm("add.rn.f32x2 %0, %1, %2;" : "=l"(r) : "l"(a), "l"(b)); return r;
}
__device__ __forceinline__ float2 up2(ull v) {
    float2 f; asm("mov.b64 {%0, %1}, %2;" : "=f"(f.x), "=f"(f.y) : "l"(v)); return f;
}
__device__ __forceinline__ unsigned s2u(const void* p) {
    return (unsigned)__cvta_generic_to_shared(p);
}
__device__ __forceinline__ void cp4(unsigned dst, const float* src) {
    asm volatile("cp.async.ca.shared.global [%0], [%1], 4;" :: "r"(dst), "l"(src));
}
__device__ __forceinline__ void cp16(unsigned dst, const float* src) {
    asm volatile("cp.async.cg.shared.global [%0], [%1], 16;" :: "r"(dst), "l"(src));
}
#define CP_COMMIT() asm volatile("cp.async.commit_group;")
#define CP_WAIT1()  asm volatile("cp.async.wait_group 1;")
#define CP_WAIT0()  asm volatile("cp.async.wait_group 0;")

// Register/shfl GAT attention + final reduction for one row.
// acc[cc][np] = {hp[2np][col], hp[2np+1][col]}, col = 4*l+cc.
__device__ __forceinline__ void phaseE(const ull acc[4][4],
                                       const float* __restrict__ swdR,
                                       const float* __restrict__ sAR,
                                       float4 a1, float4 a2, int l,
                                       float* __restrict__ out, int rowIdx, bool valid)
{
    const int hh = l >> 3, dc = l & 7, gb = l & 24;
    const float a1c[4] = {a1.x, a1.y, a1.z, a1.w};
    const float a2c[4] = {a2.x, a2.y, a2.z, a2.w};

    // 1) partial e_i / e_j dots
    ull eip[4], ejp[4];
    #pragma unroll
    for (int np = 0; np < 4; np++) { eip[np] = 0ull; ejp[np] = 0ull; }
    #pragma unroll
    for (int cc = 0; cc < 4; cc++) {
        ull ai = dup2(a1c[cc]), aj = dup2(a2c[cc]);
        #pragma unroll
        for (int np = 0; np < 4; np++) {
            fma2(eip[np], ai, acc[cc][np]);
            fma2(ejp[np], aj, acc[cc][np]);
        }
    }
    // 2) reduce across the 8-lane h-group
    #pragma unroll
    for (int off = 1; off < 8; off <<= 1) {
        #pragma unroll
        for (int np = 0; np < 4; np++) {
            eip[np] = add2(eip[np], __shfl_xor_sync(0xffffffffu, eip[np], off));
            ejp[np] = add2(ejp[np], __shfl_xor_sync(0xffffffffu, ejp[np], off));
        }
    }
    float ei[8], ej[8];
    #pragma unroll
    for (int np = 0; np < 4; np++) {
        float2 t = up2(eip[np]); ei[2*np] = t.x; ei[2*np+1] = t.y;
        float2 u = up2(ejp[np]); ej[2*np] = u.x; ej[2*np+1] = u.y;
    }
    // 3) softmax of attention row i = dc
    float eii = (dc & 4) ? ((dc & 2) ? ((dc & 1) ? ei[7] : ei[6]) : ((dc & 1) ? ei[5] : ei[4]))
                         : ((dc & 2) ? ((dc & 1) ? ei[3] : ei[2]) : ((dc & 1) ? ei[1] : ei[0]));
    float e[8], mx = -3.4e38f;
    #pragma unroll
    for (int j = 0; j < 8; j++) {
        float t = eii + ej[j];
        t = fmaxf(t, 0.2f * t);           // leaky relu
        e[j] = t; mx = fmaxf(mx, t);
    }
    float ssum = 0.f;
    #pragma unroll
    for (int j = 0; j < 8; j++) { e[j] = __expf(e[j] - mx); ssum += e[j]; }
    float inv = 1.f / ssum;
    #pragma unroll
    for (int j = 0; j < 8; j++) e[j] *= inv;
    ull anp[4];
    #pragma unroll
    for (int np = 0; np < 4; np++) anp[np] = pk2(e[2*np], e[2*np+1]);

    // 4) per-i weighted sums, elu, w_dvd partial dot
    float4 wd4 = *(const float4*)(swdR + hh * 36 + 4 * dc);
    const float wdc[4] = {wd4.x, wd4.y, wd4.z, wd4.w};
    float wp[8];
    #pragma unroll
    for (int ip = 0; ip < 8; ip++) {
        int src = gb + ip;
        ull ap0 = __shfl_sync(0xffffffffu, anp[0], src);
        ull ap1 = __shfl_sync(0xffffffffu, anp[1], src);
        ull ap2 = __shfl_sync(0xffffffffu, anp[2], src);
        ull ap3 = __shfl_sync(0xffffffffu, anp[3], src);
        float accw = 0.f;
        #pragma unroll
        for (int cc = 0; cc < 4; cc++) {
            ull g2 = 0ull;
            fma2(g2, ap0, acc[cc][0]);
            fma2(g2, ap1, acc[cc][1]);
            fma2(g2, ap2, acc[cc][2]);
            fma2(g2, ap3, acc[cc][3]);
            float2 gh = up2(g2);
            float g = gh.x + gh.y;
            g = (g > 0.f) ? g : (__expf(g) - 1.f);   // elu
            accw = fmaf(wdc[cc], g, accw);
        }
        wp[ip] = accw;
    }
    // 5) packed f32x2 butterfly over h-group d-partials
    ull wpp[4];
    #pragma unroll
    for (int q = 0; q < 4; q++) wpp[q] = pk2(wp[2*q], wp[2*q+1]);
    #pragma unroll
    for (int off = 1; off < 8; off <<= 1)
        #pragma unroll
        for (int q = 0; q < 4; q++)
            wpp[q] = add2(wpp[q], __shfl_xor_sync(0xffffffffu, wpp[q], off));

    float4 ad0 = *(const float4*)(sAR);
    float4 ad1 = *(const float4*)(sAR + 4);
    float advsum = sAR[8];
    const float adc[8] = {ad0.x, ad0.y, ad0.z, ad0.w, ad1.x, ad1.y, ad1.z, ad1.w};
    float p = 0.f;
    #pragma unroll
    for (int q = 0; q < 4; q++) {
        float2 w2 = up2(wpp[q]);
        p = fmaf(adc[2*q],     fabsf(w2.x), p);
        p = fmaf(adc[2*q + 1], fabsf(w2.y), p);
    }
    p += __shfl_xor_sync(0xffffffffu, p, 8);
    p += __shfl_xor_sync(0xffffffffu, p, 16);      // sum over 4 heads
    if (l == 0 && valid) out[rowIdx] = 0.25f * p - advsum;
}

// D-phase 64-iteration dual-row accumulation loop.
#define D_LOOP(ACC0, ACC1)                                                     \
    _Pragma("unroll")                                                          \
    for (int cc = 0; cc < 4; cc++)                                             \
        _Pragma("unroll")                                                      \
        for (int np = 0; np < 4; np++) { ACC0[cc][np] = 0ull; ACC1[cc][np] = 0ull; } \
    _Pragma("unroll 4")                                                        \
    for (int i = 0; i < 64; i++) {                                             \
        float4 wg = __ldg((const float4*)(Wg + i * 128 + 4 * l));              \
        ull w0 = dup2(wg.x), w1 = dup2(wg.y), w2 = dup2(wg.z), w3 = dup2(wg.w);\
        ulonglong2 hA0 = *(const ulonglong2*)(sT0 + i * 12);                   \
        ulonglong2 hA1 = *(const ulonglong2*)(sT0 + i * 12 + 4);               \
        ulonglong2 hB0 = *(const ulonglong2*)(sT1 + i * 12);                   \
        ulonglong2 hB1 = *(const ulonglong2*)(sT1 + i * 12 + 4);               \
        ull pA[4] = {hA0.x, hA0.y, hA1.x, hA1.y};                              \
        ull pB[4] = {hB0.x, hB0.y, hB1.x, hB1.y};                              \
        _Pragma("unroll")                                                      \
        for (int np = 0; np < 4; np++) {                                       \
            fma2(ACC0[0][np], pA[np], w0); fma2(ACC0[1][np], pA[np], w1);      \
            fma2(ACC0[2][np], pA[np], w2); fma2(ACC0[3][np], pA[np], w3);      \
            fma2(ACC1[0][np], pB[np], w0); fma2(ACC1[1][np], pB[np], w1);      \
            fma2(ACC1[2][np], pB[np], w2); fma2(ACC1[3][np], pB[np], w3);      \
        }                                                                      \
    }

// Issue async transposed H staging for two rows into sT0/sT1 (R10-verified
// map: coalesced global reads; smem write conflicts are the cheaper side).
#define STAGE_H_ASYNC(R0, R1)                                                  \
    {                                                                          \
        const float* h0p = Hg + (size_t)(R0) * 512;                            \
        const float* h1p = Hg + (size_t)(R1) * 512;                            \
        _Pragma("unroll")                                                      \
        for (int c = 0; c < 16; c++) {                                         \
            int t = c * 32 + l, n = t >> 6, i = t & 63;                        \
            cp4(uT0 + (unsigned)(i * 12 + n) * 4u, h0p + t);                   \
            cp4(uT1 + (unsigned)(i * 12 + n) * 4u, h1p + t);                   \
        }                                                                      \
        CP_COMMIT();                                                           \
    }

// Async-stage S (16B .cg) for the 4 rows of task with base row B0 (clamped).
#define STAGE_S_ASYNC(B0)                                                      \
    {                                                                          \
        _Pragma("unroll")                                                      \
        for (int r = 0; r < 4; r++) {                                          \
            int row = (B0) + r; row = row < B ? row : Bm1;                     \
            const float* sp = Sg + (size_t)row * 168;                          \
            for (int t = l; t < 42; t += 32)                                   \
                cp16(uS + (unsigned)(r * 168 + t * 4) * 4u, sp + t * 4);       \
        }                                                                      \
        CP_COMMIT();                                                           \
    }

__global__ void __launch_bounds__(NWARPS * 32, 4)
dvd_kernel(float* __restrict__ out,
           const float* __restrict__ Qv,  const float* __restrict__ Sg,
           const float* __restrict__ MQ,  const float* __restrict__ Hg,
           const float* __restrict__ w1f, const float* __restrict__ b1f,
           const float* __restrict__ w2f, const float* __restrict__ b2f,
           const float* __restrict__ Wg,  const float* __restrict__ attA,
           const float* __restrict__ Wd,  const float* __restrict__ bd,
           int B)
{
    extern __shared__ float sm[];
    const int l  = threadIdx.x & 31;
    const int wz = threadIdx.x >> 5;
    float* wb = sm + wz * WARP_FLOATS;

    const int T = (B + 3) >> 2;                    // tasks (4 rows each)
    const int W = gridDim.x * NWARPS;              // total persistent warps
    int task = blockIdx.x * NWARPS + wz;
    if (task >= T) return;
    const int Bm1 = B - 1;

    float* sS  = wb;
    float* sT0 = wb + 672;
    float* sT1 = wb + 672 + 768;
    float* swd = wb + 2208;
    float* sh1 = wb + 2208;         // aliases swd region during B tail ONLY
    float* sA  = wb + 2800;
    const unsigned uS  = s2u(sS);
    const unsigned uT0 = s2u(sT0);
    const unsigned uT1 = s2u(sT1);

    // ---- task-invariant hoists --------------------------------------------
    ull biInit;
    { float2 b2 = *(const float2*)(b1f + 2 * l); biInit = pk2(b2.x, b2.y); }
    const float4 b4 = __ldg((const float4*)(bd + 4 * l));
    const float bias2 = __ldg(b2f + (l & 7));
    const int hE = l >> 3, dE = l & 7;
    const float4 a1 = __ldg((const float4*)(attA + hE * 64 + 4 * dE));
    const float4 a2 = __ldg((const float4*)(attA + hE * 64 + 32 + 4 * dE));

    // ---- prologue: stage first task's S (group) + H01 (group) -------------
    {
        int b0 = task * 4;
        STAGE_S_ASYNC(b0);
        int h0 = b0, h1 = b0 + 1 < B ? b0 + 1 : Bm1;
        STAGE_H_ASYNC(h0, h1);
    }

    for (; task < T; task += W) {
        const int base = task * 4;
        int rr[4]; bool vv[4];
        #pragma unroll
        for (int r = 0; r < 4; r++) { int x = base + r; vv[r] = x < B; rr[r] = vv[r] ? x : Bm1; }
        const bool hasNext = (task + W) < T;

        CP_WAIT1();                  // S landed; H01 may still fly under B+C
        __syncwarp();

        // ---------------- Phase B+C fused -----------------------------------
        {
            ull a[4];
            #pragma unroll
            for (int r = 0; r < 4; r++) a[r] = biInit;
            ull cA[4][2];
            #pragma unroll
            for (int r = 0; r < 4; r++) { cA[r][0] = pk2(b4.x, b4.y); cA[r][1] = pk2(b4.z, b4.w); }

            #pragma unroll 2
            for (int k = 0; k < 168; k += 4) {
                float sv[4][4];
                #pragma unroll
                for (int r = 0; r < 4; r++) {
                    float4 s4 = *(const float4*)(sS + r * 168 + k);
                    sv[r][0] = s4.x; sv[r][1] = s4.y; sv[r][2] = s4.z; sv[r][3] = s4.w;
                }
                #pragma unroll
                for (int m = 0; m < 4; m++) {
                    float2 w1 = *(const float2*)(w1f + (k + m) * 64 + 2 * l);
                    float4 wv = __ldg((const float4*)(Wd + (k + m) * 128 + 4 * l));
                    ull wpk = pk2(w1.x, w1.y);
                    ull wp0 = pk2(wv.x, wv.y), wp1 = pk2(wv.z, wv.w);
                    #pragma unroll
                    for (int r = 0; r < 4; r++) {
                        ull d = dup2(sv[r][m]);
                        fma2(a[r],     d, wpk);
                        fma2(cA[r][0], d, wp0);
                        fma2(cA[r][1], d, wp1);
                    }
                }
            }

            // ---- B tail: relu, second layer, adv ----
            #pragma unroll
            for (int r = 0; r < 4; r++) {
                float2 f = up2(a[r]);
                *(float2*)(sh1 + r * 68 + 2 * l) = make_float2(fmaxf(f.x, 0.f), fmaxf(f.y, 0.f));
            }
            __syncwarp();
            {
                const int r = l >> 3, aa = l & 7;
                float acc2 = bias2;
                #pragma unroll 4
                for (int k = 0; k < 64; k += 4) {
                    float4 h4 = *(const float4*)(sh1 + r * 68 + k);
                    acc2 = fmaf(h4.x, __ldg(w2f + (k    ) * 8 + aa), acc2);
                    acc2 = fmaf(h4.y, __ldg(w2f + (k + 1) * 8 + aa), acc2);
                    acc2 = fmaf(h4.z, __ldg(w2f + (k + 2) * 8 + aa), acc2);
                    acc2 = fmaf(h4.w, __ldg(w2f + (k + 3) * 8 + aa), acc2);
                }
                float wf = fabsf(acc2) + 1e-10f;
                int rg = rr[r];
                float adv = wf * (__ldg(Qv + (size_t)rg * 8 + aa) - __ldg(MQ + (size_t)rg * 8 + aa));
                float asum = adv;
                asum += __shfl_xor_sync(0xffffffffu, asum, 1);
                asum += __shfl_xor_sync(0xffffffffu, asum, 2);
                asum += __shfl_xor_sync(0xffffffffu, asum, 4);
                sA[r * 12 + aa] = adv;
                if (aa == 0) sA[r * 12 + 8] = asum;
            }
            __syncwarp();             // sh1 consumed before C tail overwrites swd

            // ---- C tail: store w_dvd ----
            const int hh = l >> 3, dd = 4 * (l & 7);
            #pragma unroll
            for (int r = 0; r < 4; r++) {
                float2 x0 = up2(cA[r][0]), x1 = up2(cA[r][1]);
                *(float4*)(swd + r * 148 + hh * 36 + dd) = make_float4(x0.x, x0.y, x1.x, x1.y);
            }
            __syncwarp();
        }

        ull acc0[4][4], acc1[4][4];

        // ---------------- Pass 0: rows 0,1 ----------------------------------
        CP_WAIT0();                  // H01 landed
        __syncwarp();
        D_LOOP(acc0, acc1);
        phaseE(acc0, swd, sA, a1, a2, l, out, base, vv[0]);
        __syncwarp();                // all lanes past D-loop sT reads
        STAGE_H_ASYNC(rr[2], rr[3]); // H23 flies under phaseE(row1)
        phaseE(acc1, swd + 148, sA + 12, a1, a2, l, out, base + 1, vv[1]);

        // ---------------- Pass 1: rows 2,3 ----------------------------------
        CP_WAIT0();                  // H23 landed
        __syncwarp();
        D_LOOP(acc0, acc1);
        __syncwarp();                // sT/sS dead: safe to stage next task
        if (hasNext) {               // next task's S + H01 fly under phaseEs
            int nb = (task + W) * 4;
            STAGE_S_ASYNC(nb);
            int h0 = nb, h1 = nb + 1 < B ? nb + 1 : Bm1;
            STAGE_H_ASYNC(h0, h1);
        }
        phaseE(acc0, swd + 2 * 148, sA + 2 * 12, a1, a2, l, out, base + 2, vv[2]);
        phaseE(acc1, swd + 3 * 148, sA + 3 * 12, a1, a2, l, out, base + 3, vv[3]);
    }
}

extern "C" void kernel_launch(void* const* d_in, const int* in_sizes, int n_in,
                              void* d_out, int out_size)
{
    const float* Qv   = (const float*)d_in[0];   // agent_qs
    const float* S    = (const float*)d_in[1];   // states
    const float* MQ   = (const float*)d_in[2];   // max_q_i
    const float* H    = (const float*)d_in[3];   // hidden_states
    const float* w1f  = (const float*)d_in[4];
    const float* b1f  = (const float*)d_in[5];
    const float* w2f  = (const float*)d_in[6];
    const float* b2f  = (const float*)d_in[7];
    // d_in[8..11] = w1v,b1v,w2v,b2v : cancel algebraically in adv_q, unused
    const float* Wg   = (const float*)d_in[12];
    const float* attA = (const float*)d_in[13];
    const float* Wd   = (const float*)d_in[14];
    const float* bd   = (const float*)d_in[15];

    int B = in_sizes[0] / 8;                      // bs*T rows
    int T = (B + 3) / 4;
    int grid = T < 608 ? T : 608;                 // persistent: 4 blocks x 152 SMs
    size_t smem = (size_t)NWARPS * WARP_FLOATS * sizeof(float);

    dvd_kernel<<<grid, NWARPS * 32, smem>>>((float*)d_out, Qv, S, MQ, H,
                                            w1f, b1f, w2f, b2f, Wg, attA, Wd, bd, B);
}

// round 15
// speedup vs baseline: 1.1712x; 1.1712x over previous
#include <cuda_runtime.h>

typedef unsigned long long ull;

#define NWARPS 4
// per-warp smem floats (2848):
//  sS  @0    (672  = 4*168)            per-row S
//  sT  @672  (1536 = 2*768, H^T stride 12)
//  swd @2208 (592  = 4*148)  [r][h*36+d]   (sh1 272 floats aliases swd during B tail)
//  sA  @2800 (48   = 4*12)   [r][0..7]=adv, [r][8]=sum(adv)
#define WARP_FLOATS 2848

__device__ __forceinline__ ull pk2(float x, float y) {
    ull r; asm("mov.b64 %0, {%1, %2};" : "=l"(r) : "f"(x), "f"(y)); return r;
}
__device__ __forceinline__ ull dup2(float x) {
    ull r; asm("mov.b64 %0, {%1, %1};" : "=l"(r) : "f"(x)); return r;
}
__device__ __forceinline__ void fma2(ull& d, ull a, ull b) {
    asm("fma.rn.f32x2 %0, %1, %2, %0;" : "+l"(d) : "l"(a), "l"(b));
}
__device__ __forceinline__ ull add2(ull a, ull b) {
    ull r; asm("add.rn.f32x2 %0, %1, %2;" : "=l"(r) : "l"(a), "l"(b)); return r;
}
__device__ __forceinline__ float2 up2(ull v) {
    float2 f; asm("mov.b64 {%0, %1}, %2;" : "=f"(f.x), "=f"(f.y) : "l"(v)); return f;
}
__device__ __forceinline__ unsigned s2u(const void* p) {
    return (unsigned)__cvta_generic_to_shared(p);
}
__device__ __forceinline__ void cp4(unsigned dst, const float* src) {
    asm volatile("cp.async.ca.shared.global [%0], [%1], 4;" :: "r"(dst), "l"(src));
}
__device__ __forceinline__ void cp16(unsigned dst, const float* src) {
    asm volatile("cp.async.cg.shared.global [%0], [%1], 16;" :: "r"(dst), "l"(src));
}
#define CP_COMMIT() asm volatile("cp.async.commit_group;")
#define CP_WAIT1()  asm volatile("cp.async.wait_group 1;")
#define CP_WAIT0()  asm volatile("cp.async.wait_group 0;")

// Register/shfl GAT attention + final reduction for one row.
// acc[cc][np] = {hp[2np][col], hp[2np+1][col]}, col = 4*l+cc.
__device__ __forceinline__ void phaseE(const ull acc[4][4],
                                       const float* __restrict__ swdR,
                                       const float* __restrict__ sAR,
                                       float4 a1, float4 a2, int l,
                                       float* __restrict__ out, int rowIdx, bool valid)
{
    const int hh = l >> 3, dc = l & 7, gb = l & 24;
    const float a1c[4] = {a1.x, a1.y, a1.z, a1.w};
    const float a2c[4] = {a2.x, a2.y, a2.z, a2.w};

    // 1) partial e_i / e_j dots
    ull eip[4], ejp[4];
    #pragma unroll
    for (int np = 0; np < 4; np++) { eip[np] = 0ull; ejp[np] = 0ull; }
    #pragma unroll
    for (int cc = 0; cc < 4; cc++) {
        ull ai = dup2(a1c[cc]), aj = dup2(a2c[cc]);
        #pragma unroll
        for (int np = 0; np < 4; np++) {
            fma2(eip[np], ai, acc[cc][np]);
            fma2(ejp[np], aj, acc[cc][np]);
        }
    }
    // 2) reduce across the 8-lane h-group
    #pragma unroll
    for (int off = 1; off < 8; off <<= 1) {
        #pragma unroll
        for (int np = 0; np < 4; np++) {
            eip[np] = add2(eip[np], __shfl_xor_sync(0xffffffffu, eip[np], off));
            ejp[np] = add2(ejp[np], __shfl_xor_sync(0xffffffffu, ejp[np], off));
        }
    }
    float ei[8], ej[8];
    #pragma unroll
    for (int np = 0; np < 4; np++) {
        float2 t = up2(eip[np]); ei[2*np] = t.x; ei[2*np+1] = t.y;
        float2 u = up2(ejp[np]); ej[2*np] = u.x; ej[2*np+1] = u.y;
    }
    // 3) softmax of attention row i = dc
    float eii = (dc & 4) ? ((dc & 2) ? ((dc & 1) ? ei[7] : ei[6]) : ((dc & 1) ? ei[5] : ei[4]))
                         : ((dc & 2) ? ((dc & 1) ? ei[3] : ei[2]) : ((dc & 1) ? ei[1] : ei[0]));
    float e[8], mx = -3.4e38f;
    #pragma unroll
    for (int j = 0; j < 8; j++) {
        float t = eii + ej[j];
        t = fmaxf(t, 0.2f * t);           // leaky relu
        e[j] = t; mx = fmaxf(mx, t);
    }
    float ssum = 0.f;
    #pragma unroll
    for (int j = 0; j < 8; j++) { e[j] = __expf(e[j] - mx); ssum += e[j]; }
    float inv = 1.f / ssum;
    #pragma unroll
    for (int j = 0; j < 8; j++) e[j] *= inv;
    ull anp[4];
    #pragma unroll
    for (int np = 0; np < 4; np++) anp[np] = pk2(e[2*np], e[2*np+1]);

    // 4) per-i weighted sums, elu, w_dvd partial dot
    float4 wd4 = *(const float4*)(swdR + hh * 36 + 4 * dc);
    const float wdc[4] = {wd4.x, wd4.y, wd4.z, wd4.w};
    float wp[8];
    #pragma unroll
    for (int ip = 0; ip < 8; ip++) {
        int src = gb + ip;
        ull ap0 = __shfl_sync(0xffffffffu, anp[0], src);
        ull ap1 = __shfl_sync(0xffffffffu, anp[1], src);
        ull ap2 = __shfl_sync(0xffffffffu, anp[2], src);
        ull ap3 = __shfl_sync(0xffffffffu, anp[3], src);
        float accw = 0.f;
        #pragma unroll
        for (int cc = 0; cc < 4; cc++) {
            ull g2 = 0ull;
            fma2(g2, ap0, acc[cc][0]);
            fma2(g2, ap1, acc[cc][1]);
            fma2(g2, ap2, acc[cc][2]);
            fma2(g2, ap3, acc[cc][3]);
            float2 gh = up2(g2);
            float g = gh.x + gh.y;
            g = (g > 0.f) ? g : (__expf(g) - 1.f);   // elu
            accw = fmaf(wdc[cc], g, accw);
        }
        wp[ip] = accw;
    }
    // 5) packed f32x2 butterfly over h-group d-partials
    ull wpp[4];
    #pragma unroll
    for (int q = 0; q < 4; q++) wpp[q] = pk2(wp[2*q], wp[2*q+1]);
    #pragma unroll
    for (int off = 1; off < 8; off <<= 1)
        #pragma unroll
        for (int q = 0; q < 4; q++)
            wpp[q] = add2(wpp[q], __shfl_xor_sync(0xffffffffu, wpp[q], off));

    float4 ad0 = *(const float4*)(sAR);
    float4 ad1 = *(const float4*)(sAR + 4);
    float advsum = sAR[8];
    const float adc[8] = {ad0.x, ad0.y, ad0.z, ad0.w, ad1.x, ad1.y, ad1.z, ad1.w};
    float p = 0.f;
    #pragma unroll
    for (int q = 0; q < 4; q++) {
        float2 w2 = up2(wpp[q]);
        p = fmaf(adc[2*q],     fabsf(w2.x), p);
        p = fmaf(adc[2*q + 1], fabsf(w2.y), p);
    }
    p += __shfl_xor_sync(0xffffffffu, p, 8);
    p += __shfl_xor_sync(0xffffffffu, p, 16);      // sum over 4 heads
    if (l == 0 && valid) out[rowIdx] = 0.25f * p - advsum;
}

// D-phase 64-iteration dual-row accumulation loop.
#define D_LOOP(ACC0, ACC1)                                                     \
    _Pragma("unroll")                                                          \
    for (int cc = 0; cc < 4; cc++)                                             \
        _Pragma("unroll")                                                      \
        for (int np = 0; np < 4; np++) { ACC0[cc][np] = 0ull; ACC1[cc][np] = 0ull; } \
    _Pragma("unroll 4")                                                        \
    for (int i = 0; i < 64; i++) {                                             \
        float4 wg = __ldg((const float4*)(Wg + i * 128 + 4 * l));              \
        ull w0 = dup2(wg.x), w1 = dup2(wg.y), w2 = dup2(wg.z), w3 = dup2(wg.w);\
        ulonglong2 hA0 = *(const ulonglong2*)(sT0 + i * 12);                   \
        ulonglong2 hA1 = *(const ulonglong2*)(sT0 + i * 12 + 4);               \
        ulonglong2 hB0 = *(const ulonglong2*)(sT1 + i * 12);                   \
        ulonglong2 hB1 = *(const ulonglong2*)(sT1 + i * 12 + 4);               \
        ull pA[4] = {hA0.x, hA0.y, hA1.x, hA1.y};                              \
        ull pB[4] = {hB0.x, hB0.y, hB1.x, hB1.y};                              \
        _Pragma("unroll")                                                      \
        for (int np = 0; np < 4; np++) {                                       \
            fma2(ACC0[0][np], pA[np], w0); fma2(ACC0[1][np], pA[np], w1);      \
            fma2(ACC0[2][np], pA[np], w2); fma2(ACC0[3][np], pA[np], w3);      \
            fma2(ACC1[0][np], pB[np], w0); fma2(ACC1[1][np], pB[np], w1);      \
            fma2(ACC1[2][np], pB[np], w2); fma2(ACC1[3][np], pB[np], w3);      \
        }                                                                      \
    }

// Issue async transposed H staging for two rows into sT0/sT1.
// (R10-verified map: coalesced global reads; smem write conflicts are the
//  cheaper side — the R11 "fix" that inverted this tradeoff regressed 1.66x.)
#define STAGE_H_ASYNC(R0, R1)                                                  \
    {                                                                          \
        const float* h0p = Hg + (size_t)(R0) * 512;                            \
        const float* h1p = Hg + (size_t)(R1) * 512;                            \
        _Pragma("unroll")                                                      \
        for (int c = 0; c < 16; c++) {                                         \
            int t = c * 32 + l, n = t >> 6, i = t & 63;                        \
            cp4(uT0 + (unsigned)(i * 12 + n) * 4u, h0p + t);                   \
            cp4(uT1 + (unsigned)(i * 12 + n) * 4u, h1p + t);                   \
        }                                                                      \
        CP_COMMIT();                                                           \
    }

__global__ void __launch_bounds__(NWARPS * 32, 4)
dvd_kernel(float* __restrict__ out,
           const float* __restrict__ Qv,  const float* __restrict__ Sg,
           const float* __restrict__ MQ,  const float* __restrict__ Hg,
           const float* __restrict__ w1f, const float* __restrict__ b1f,
           const float* __restrict__ w2f, const float* __restrict__ b2f,
           const float* __restrict__ Wg,  const float* __restrict__ attA,
           const float* __restrict__ Wd,  const float* __restrict__ bd,
           int B)
{
    extern __shared__ float sm[];
    const int l  = threadIdx.x & 31;
    const int wz = threadIdx.x >> 5;
    float* wb = sm + wz * WARP_FLOATS;

    const int base = (blockIdx.x * NWARPS + wz) * 4;
    if (base >= B) return;
    const int Bm1 = B - 1;
    int rr[4]; bool vv[4];
    #pragma unroll
    for (int r = 0; r < 4; r++) { int x = base + r; vv[r] = x < B; rr[r] = vv[r] ? x : Bm1; }

    float* sS  = wb;
    float* sT0 = wb + 672;
    float* sT1 = wb + 672 + 768;
    float* swd = wb + 2208;
    float* sh1 = wb + 2208;         // aliases swd region during B tail ONLY
    float* sA  = wb + 2800;
    const unsigned uS  = s2u(sS);
    const unsigned uT0 = s2u(sT0);
    const unsigned uT1 = s2u(sT1);

    // ---------------- Phase A: async-stage S (group 1, 16B .cg) + H rows 0,1
    #pragma unroll
    for (int r = 0; r < 4; r++) {
        const float* sp = Sg + (size_t)rr[r] * 168;
        for (int t = l; t < 42; t += 32)
            cp16(uS + (unsigned)(r * 168 + t * 4) * 4u, sp + t * 4);
    }
    CP_COMMIT();
    STAGE_H_ASYNC(rr[0], rr[1]);
    CP_WAIT1();                      // S landed; H01 still in flight under B+C
    __syncwarp();

    // ---------------- Phase B+C fused: hidden layer AND w_dvd in one S pass
    {
        ull a[4];
        {
            float2 b2 = *(const float2*)(b1f + 2 * l);
            ull bi = pk2(b2.x, b2.y);
            #pragma unroll
            for (int r = 0; r < 4; r++) a[r] = bi;
        }
        float4 b4 = __ldg((const float4*)(bd + 4 * l));
        ull cA[4][2];
        #pragma unroll
        for (int r = 0; r < 4; r++) { cA[r][0] = pk2(b4.x, b4.y); cA[r][1] = pk2(b4.z, b4.w); }

        #pragma unroll 2
        for (int k = 0; k < 168; k += 4) {
            float sv[4][4];
            #pragma unroll
            for (int r = 0; r < 4; r++) {
                float4 s4 = *(const float4*)(sS + r * 168 + k);
                sv[r][0] = s4.x; sv[r][1] = s4.y; sv[r][2] = s4.z; sv[r][3] = s4.w;
            }
            #pragma unroll
            for (int m = 0; m < 4; m++) {
                float2 w1 = *(const float2*)(w1f + (k + m) * 64 + 2 * l);
                float4 wv = __ldg((const float4*)(Wd + (k + m) * 128 + 4 * l));
                ull wpk = pk2(w1.x, w1.y);
                ull wp0 = pk2(wv.x, wv.y), wp1 = pk2(wv.z, wv.w);
                #pragma unroll
                for (int r = 0; r < 4; r++) {
                    ull d = dup2(sv[r][m]);
                    fma2(a[r],     d, wpk);      // hypernet hidden layer
                    fma2(cA[r][0], d, wp0);      // w_dvd
                    fma2(cA[r][1], d, wp1);
                }
            }
        }

        // ---- B tail: relu, second layer, adv (sh1 lives in swd region) ----
        #pragma unroll
        for (int r = 0; r < 4; r++) {
            float2 f = up2(a[r]);
            *(float2*)(sh1 + r * 68 + 2 * l) = make_float2(fmaxf(f.x, 0.f), fmaxf(f.y, 0.f));
        }
        __syncwarp();
        {
            const int r = l >> 3, aa = l & 7;
            float acc2 = __ldg(b2f + aa);
            #pragma unroll 4
            for (int k = 0; k < 64; k += 4) {
                float4 h4 = *(const float4*)(sh1 + r * 68 + k);
                acc2 = fmaf(h4.x, __ldg(w2f + (k    ) * 8 + aa), acc2);
                acc2 = fmaf(h4.y, __ldg(w2f + (k + 1) * 8 + aa), acc2);
                acc2 = fmaf(h4.z, __ldg(w2f + (k + 2) * 8 + aa), acc2);
                acc2 = fmaf(h4.w, __ldg(w2f + (k + 3) * 8 + aa), acc2);
            }
            float wf = fabsf(acc2) + 1e-10f;
            int rg = rr[r];
            float adv = wf * (__ldg(Qv + (size_t)rg * 8 + aa) - __ldg(MQ + (size_t)rg * 8 + aa));
            float asum = adv;
            asum += __shfl_xor_sync(0xffffffffu, asum, 1);
            asum += __shfl_xor_sync(0xffffffffu, asum, 2);
            asum += __shfl_xor_sync(0xffffffffu, asum, 4);
            sA[r * 12 + aa] = adv;
            if (aa == 0) sA[r * 12 + 8] = asum;
        }
        __syncwarp();                 // sh1 fully consumed before C tail overwrites swd

        // ---- C tail: store w_dvd ----
        const int hh = l >> 3, dd = 4 * (l & 7);
        #pragma unroll
        for (int r = 0; r < 4; r++) {
            float2 x0 = up2(cA[r][0]), x1 = up2(cA[r][1]);
            *(float4*)(swd + r * 148 + hh * 36 + dd) = make_float4(x0.x, x0.y, x1.x, x1.y);
        }
        __syncwarp();
    }

    // attA coefficients for this lane (reused for all 4 rows)
    const int hE = l >> 3, dE = l & 7;
    float4 a1 = __ldg((const float4*)(attA + hE * 64 + 4 * dE));
    float4 a2 = __ldg((const float4*)(attA + hE * 64 + 32 + 4 * dE));

    ull acc0[4][4], acc1[4][4];

    // ---------------- Pass 0: rows 0,1 ------------------------------------
    CP_WAIT0();                      // H01 landed
    __syncwarp();
    D_LOOP(acc0, acc1);
    phaseE(acc0, swd, sA, a1, a2, l, out, base, vv[0]);
    __syncwarp();                    // all lanes past D-loop sT reads
    STAGE_H_ASYNC(rr[2], rr[3]);     // H23 flies under phaseE(row1)
    phaseE(acc1, swd + 148, sA + 12, a1, a2, l, out, base + 1, vv[1]);

    // ---------------- Pass 1: rows 2,3 ------------------------------------
    CP_WAIT0();
    __syncwarp();
    D_LOOP(acc0, acc1);
    phaseE(acc0, swd + 2 * 148, sA + 2 * 12, a1, a2, l, out, base + 2, vv[2]);
    phaseE(acc1, swd + 3 * 148, sA + 3 * 12, a1, a2, l, out, base + 3, vv[3]);
}

extern "C" void kernel_launch(void* const* d_in, const int* in_sizes, int n_in,
                              void* d_out, int out_size)
{
    const float* Qv   = (const float*)d_in[0];   // agent_qs
    const float* S    = (const float*)d_in[1];   // states
    const float* MQ   = (const float*)d_in[2];   // max_q_i
    const float* H    = (const float*)d_in[3];   // hidden_states
    const float* w1f  = (const float*)d_in[4];
    const float* b1f  = (const float*)d_in[5];
    const float* w2f  = (const float*)d_in[6];
    const float* b2f  = (const float*)d_in[7];
    // d_in[8..11] = w1v,b1v,w2v,b2v : cancel algebraically in adv_q, unused
    const float* Wg   = (const float*)d_in[12];
    const float* attA = (const float*)d_in[13];
    const float* Wd   = (const float*)d_in[14];
    const float* bd   = (const float*)d_in[15];

    int B = in_sizes[0] / 8;                      // bs*T rows
    int rowsPerBlock = NWARPS * 4;
    int grid = (B + rowsPerBlock - 1) / rowsPerBlock;
    size_t smem = (size_t)NWARPS * WARP_FLOATS * sizeof(float);

    dvd_kernel<<<grid, NWARPS * 32, smem>>>((float*)d_out, Qv, S, MQ, H,
                                            w1f, b1f, w2f, b2f, Wg, attA, Wd, bd, B);
}

// round 16
// speedup vs baseline: 1.1815x; 1.0088x over previous
#include <cuda_runtime.h>

typedef unsigned long long ull;

#define NWARPS 4
// per-warp smem floats (2848):
//  sS  @0    (672  = 4*168)            per-row S
//  sT  @672  (1536 = 2*768, H^T stride 12)
//  swd @2208 (592  = 4*148)  [r][h*36+d]   (sh1 272 floats aliases swd during B tail)
//  sA  @2800 (48   = 4*12)   [r][0..7]=adv, [r][8]=sum(adv)
#define WARP_FLOATS 2848

__device__ __forceinline__ ull pk2(float x, float y) {
    ull r; asm("mov.b64 %0, {%1, %2};" : "=l"(r) : "f"(x), "f"(y)); return r;
}
__device__ __forceinline__ ull dup2(float x) {
    ull r; asm("mov.b64 %0, {%1, %1};" : "=l"(r) : "f"(x)); return r;
}
__device__ __forceinline__ void fma2(ull& d, ull a, ull b) {
    asm("fma.rn.f32x2 %0, %1, %2, %0;" : "+l"(d) : "l"(a), "l"(b));
}
__device__ __forceinline__ ull add2(ull a, ull b) {
    ull r; asm("add.rn.f32x2 %0, %1, %2;" : "=l"(r) : "l"(a), "l"(b)); return r;
}
__device__ __forceinline__ float2 up2(ull v) {
    float2 f; asm("mov.b64 {%0, %1}, %2;" : "=f"(f.x), "=f"(f.y) : "l"(v)); return f;
}
__device__ __forceinline__ unsigned s2u(const void* p) {
    return (unsigned)__cvta_generic_to_shared(p);
}
__device__ __forceinline__ void cp4(unsigned dst, const float* src) {
    asm volatile("cp.async.ca.shared.global [%0], [%1], 4;" :: "r"(dst), "l"(src));
}
__device__ __forceinline__ void cp16(unsigned dst, const float* src) {
    asm volatile("cp.async.cg.shared.global [%0], [%1], 16;" :: "r"(dst), "l"(src));
}
#define CP_COMMIT() asm volatile("cp.async.commit_group;")
#define CP_WAIT1()  asm volatile("cp.async.wait_group 1;")
#define CP_WAIT0()  asm volatile("cp.async.wait_group 0;")

// Register/shfl GAT attention + final reduction for one row.
// acc[cc][np] = {hp[2np][col], hp[2np+1][col]}, col = 4*l+cc.
__device__ __forceinline__ void phaseE(const ull acc[4][4],
                                       const float* __restrict__ swdR,
                                       const float* __restrict__ sAR,
                                       float4 a1, float4 a2, int l,
                                       float* __restrict__ out, int rowIdx, bool valid)
{
    const int hh = l >> 3, dc = l & 7, gb = l & 24;
    const float a1c[4] = {a1.x, a1.y, a1.z, a1.w};
    const float a2c[4] = {a2.x, a2.y, a2.z, a2.w};

    // 1) partial e_i / e_j dots
    ull eip[4], ejp[4];
    #pragma unroll
    for (int np = 0; np < 4; np++) { eip[np] = 0ull; ejp[np] = 0ull; }
    #pragma unroll
    for (int cc = 0; cc < 4; cc++) {
        ull ai = dup2(a1c[cc]), aj = dup2(a2c[cc]);
        #pragma unroll
        for (int np = 0; np < 4; np++) {
            fma2(eip[np], ai, acc[cc][np]);
            fma2(ejp[np], aj, acc[cc][np]);
        }
    }
    // 2) reduce across the 8-lane h-group
    #pragma unroll
    for (int off = 1; off < 8; off <<= 1) {
        #pragma unroll
        for (int np = 0; np < 4; np++) {
            eip[np] = add2(eip[np], __shfl_xor_sync(0xffffffffu, eip[np], off));
            ejp[np] = add2(ejp[np], __shfl_xor_sync(0xffffffffu, ejp[np], off));
        }
    }
    float ei[8], ej[8];
    #pragma unroll
    for (int np = 0; np < 4; np++) {
        float2 t = up2(eip[np]); ei[2*np] = t.x; ei[2*np+1] = t.y;
        float2 u = up2(ejp[np]); ej[2*np] = u.x; ej[2*np+1] = u.y;
    }
    // 3) softmax of attention row i = dc
    float eii = (dc & 4) ? ((dc & 2) ? ((dc & 1) ? ei[7] : ei[6]) : ((dc & 1) ? ei[5] : ei[4]))
                         : ((dc & 2) ? ((dc & 1) ? ei[3] : ei[2]) : ((dc & 1) ? ei[1] : ei[0]));
    float e[8], mx = -3.4e38f;
    #pragma unroll
    for (int j = 0; j < 8; j++) {
        float t = eii + ej[j];
        t = fmaxf(t, 0.2f * t);           // leaky relu
        e[j] = t; mx = fmaxf(mx, t);
    }
    float ssum = 0.f;
    #pragma unroll
    for (int j = 0; j < 8; j++) { e[j] = __expf(e[j] - mx); ssum += e[j]; }
    float inv = 1.f / ssum;
    #pragma unroll
    for (int j = 0; j < 8; j++) e[j] *= inv;
    ull anp[4];
    #pragma unroll
    for (int np = 0; np < 4; np++) anp[np] = pk2(e[2*np], e[2*np+1]);

    // 4) per-i weighted sums, elu, w_dvd partial dot
    float4 wd4 = *(const float4*)(swdR + hh * 36 + 4 * dc);
    const float wdc[4] = {wd4.x, wd4.y, wd4.z, wd4.w};
    float wp[8];
    #pragma unroll
    for (int ip = 0; ip < 8; ip++) {
        int src = gb + ip;
        ull ap0 = __shfl_sync(0xffffffffu, anp[0], src);
        ull ap1 = __shfl_sync(0xffffffffu, anp[1], src);
        ull ap2 = __shfl_sync(0xffffffffu, anp[2], src);
        ull ap3 = __shfl_sync(0xffffffffu, anp[3], src);
        float accw = 0.f;
        #pragma unroll
        for (int cc = 0; cc < 4; cc++) {
            ull g2 = 0ull;
            fma2(g2, ap0, acc[cc][0]);
            fma2(g2, ap1, acc[cc][1]);
            fma2(g2, ap2, acc[cc][2]);
            fma2(g2, ap3, acc[cc][3]);
            float2 gh = up2(g2);
            float g = gh.x + gh.y;
            g = (g > 0.f) ? g : (__expf(g) - 1.f);   // elu
            accw = fmaf(wdc[cc], g, accw);
        }
        wp[ip] = accw;
    }
    // 5) packed f32x2 butterfly over h-group d-partials
    ull wpp[4];
    #pragma unroll
    for (int q = 0; q < 4; q++) wpp[q] = pk2(wp[2*q], wp[2*q+1]);
    #pragma unroll
    for (int off = 1; off < 8; off <<= 1)
        #pragma unroll
        for (int q = 0; q < 4; q++)
            wpp[q] = add2(wpp[q], __shfl_xor_sync(0xffffffffu, wpp[q], off));

    float4 ad0 = *(const float4*)(sAR);
    float4 ad1 = *(const float4*)(sAR + 4);
    float advsum = sAR[8];
    const float adc[8] = {ad0.x, ad0.y, ad0.z, ad0.w, ad1.x, ad1.y, ad1.z, ad1.w};
    float p = 0.f;
    #pragma unroll
    for (int q = 0; q < 4; q++) {
        float2 w2 = up2(wpp[q]);
        p = fmaf(adc[2*q],     fabsf(w2.x), p);
        p = fmaf(adc[2*q + 1], fabsf(w2.y), p);
    }
    p += __shfl_xor_sync(0xffffffffu, p, 8);
    p += __shfl_xor_sync(0xffffffffu, p, 16);      // sum over 4 heads
    if (l == 0 && valid) out[rowIdx] = 0.25f * p - advsum;
}

// D-phase 64-iteration dual-row accumulation loop (unroll 8: wider
// software-pipeline window over LDS->fma2 chains).
#define D_LOOP(ACC0, ACC1)                                                     \
    _Pragma("unroll")                                                          \
    for (int cc = 0; cc < 4; cc++)                                             \
        _Pragma("unroll")                                                      \
        for (int np = 0; np < 4; np++) { ACC0[cc][np] = 0ull; ACC1[cc][np] = 0ull; } \
    _Pragma("unroll 8")                                                        \
    for (int i = 0; i < 64; i++) {                                             \
        float4 wg = __ldg((const float4*)(Wg + i * 128 + 4 * l));              \
        ull w0 = dup2(wg.x), w1 = dup2(wg.y), w2 = dup2(wg.z), w3 = dup2(wg.w);\
        ulonglong2 hA0 = *(const ulonglong2*)(sT0 + i * 12);                   \
        ulonglong2 hA1 = *(const ulonglong2*)(sT0 + i * 12 + 4);               \
        ulonglong2 hB0 = *(const ulonglong2*)(sT1 + i * 12);                   \
        ulonglong2 hB1 = *(const ulonglong2*)(sT1 + i * 12 + 4);               \
        ull pA[4] = {hA0.x, hA0.y, hA1.x, hA1.y};                              \
        ull pB[4] = {hB0.x, hB0.y, hB1.x, hB1.y};                              \
        _Pragma("unroll")                                                      \
        for (int np = 0; np < 4; np++) {                                       \
            fma2(ACC0[0][np], pA[np], w0); fma2(ACC0[1][np], pA[np], w1);      \
            fma2(ACC0[2][np], pA[np], w2); fma2(ACC0[3][np], pA[np], w3);      \
            fma2(ACC1[0][np], pB[np], w0); fma2(ACC1[1][np], pB[np], w1);      \
            fma2(ACC1[2][np], pB[np], w2); fma2(ACC1[3][np], pB[np], w3);      \
        }                                                                      \
    }

// Issue async transposed H staging for two rows into sT0/sT1.
// (R10-verified map: coalesced global reads; smem write conflicts are the
//  cheaper side — the R11 "fix" that inverted this tradeoff regressed 1.66x.)
#define STAGE_H_ASYNC(R0, R1)                                                  \
    {                                                                          \
        const float* h0p = Hg + (size_t)(R0) * 512;                            \
        const float* h1p = Hg + (size_t)(R1) * 512;                            \
        _Pragma("unroll")                                                      \
        for (int c = 0; c < 16; c++) {                                         \
            int t = c * 32 + l, n = t >> 6, i = t & 63;                        \
            cp4(uT0 + (unsigned)(i * 12 + n) * 4u, h0p + t);                   \
            cp4(uT1 + (unsigned)(i * 12 + n) * 4u, h1p + t);                   \
        }                                                                      \
        CP_COMMIT();                                                           \
    }

__global__ void __launch_bounds__(NWARPS * 32, 4)
dvd_kernel(float* __restrict__ out,
           const float* __restrict__ Qv,  const float* __restrict__ Sg,
           const float* __restrict__ MQ,  const float* __restrict__ Hg,
           const float* __restrict__ w1f, const float* __restrict__ b1f,
           const float* __restrict__ w2f, const float* __restrict__ b2f,
           const float* __restrict__ Wg,  const float* __restrict__ attA,
           const float* __restrict__ Wd,  const float* __restrict__ bd,
           int B)
{
    extern __shared__ float sm[];
    const int l  = threadIdx.x & 31;
    const int wz = threadIdx.x >> 5;
    float* wb = sm + wz * WARP_FLOATS;

    const int base = (blockIdx.x * NWARPS + wz) * 4;
    if (base >= B) return;
    const int Bm1 = B - 1;
    int rr[4]; bool vv[4];
    #pragma unroll
    for (int r = 0; r < 4; r++) { int x = base + r; vv[r] = x < B; rr[r] = vv[r] ? x : Bm1; }

    float* sS  = wb;
    float* sT0 = wb + 672;
    float* sT1 = wb + 672 + 768;
    float* swd = wb + 2208;
    float* sh1 = wb + 2208;         // aliases swd region during B tail ONLY
    float* sA  = wb + 2800;
    const unsigned uS  = s2u(sS);
    const unsigned uT0 = s2u(sT0);
    const unsigned uT1 = s2u(sT1);

    // ---------------- Phase A: async-stage S (group 1, 16B .cg) + H rows 0,1
    #pragma unroll
    for (int r = 0; r < 4; r++) {
        const float* sp = Sg + (size_t)rr[r] * 168;
        for (int t = l; t < 42; t += 32)
            cp16(uS + (unsigned)(r * 168 + t * 4) * 4u, sp + t * 4);
    }
    CP_COMMIT();
    STAGE_H_ASYNC(rr[0], rr[1]);

    // Prefetch the DRAM-cold Qv/MQ values this lane will need in the B tail;
    // their ~577-cycle latency resolves under the entire B+C k-loop.
    const int rB = l >> 3, aaB = l & 7;
    const int rgB = rr[rB];
    const float qv_pre = __ldg(Qv + (size_t)rgB * 8 + aaB);
    const float mq_pre = __ldg(MQ + (size_t)rgB * 8 + aaB);

    CP_WAIT1();                      // S landed; H01 still in flight under B+C
    __syncwarp();

    // ---------------- Phase B+C fused: hidden layer AND w_dvd in one S pass
    {
        ull a[4];
        {
            float2 b2 = *(const float2*)(b1f + 2 * l);
            ull bi = pk2(b2.x, b2.y);
            #pragma unroll
            for (int r = 0; r < 4; r++) a[r] = bi;
        }
        float4 b4 = __ldg((const float4*)(bd + 4 * l));
        ull cA[4][2];
        #pragma unroll
        for (int r = 0; r < 4; r++) { cA[r][0] = pk2(b4.x, b4.y); cA[r][1] = pk2(b4.z, b4.w); }

        #pragma unroll 2
        for (int k = 0; k < 168; k += 4) {
            float sv[4][4];
            #pragma unroll
            for (int r = 0; r < 4; r++) {
                float4 s4 = *(const float4*)(sS + r * 168 + k);
                sv[r][0] = s4.x; sv[r][1] = s4.y; sv[r][2] = s4.z; sv[r][3] = s4.w;
            }
            #pragma unroll
            for (int m = 0; m < 4; m++) {
                float2 w1 = *(const float2*)(w1f + (k + m) * 64 + 2 * l);
                float4 wv = __ldg((const float4*)(Wd + (k + m) * 128 + 4 * l));
                ull wpk = pk2(w1.x, w1.y);
                ull wp0 = pk2(wv.x, wv.y), wp1 = pk2(wv.z, wv.w);
                #pragma unroll
                for (int r = 0; r < 4; r++) {
                    ull d = dup2(sv[r][m]);
                    fma2(a[r],     d, wpk);      // hypernet hidden layer
                    fma2(cA[r][0], d, wp0);      // w_dvd
                    fma2(cA[r][1], d, wp1);
                }
            }
        }

        // ---- B tail: relu, second layer, adv (sh1 lives in swd region) ----
        #pragma unroll
        for (int r = 0; r < 4; r++) {
            float2 f = up2(a[r]);
            *(float2*)(sh1 + r * 68 + 2 * l) = make_float2(fmaxf(f.x, 0.f), fmaxf(f.y, 0.f));
        }
        __syncwarp();
        {
            float acc2 = __ldg(b2f + aaB);
            #pragma unroll 4
            for (int k = 0; k < 64; k += 4) {
                float4 h4 = *(const float4*)(sh1 + rB * 68 + k);
                acc2 = fmaf(h4.x, __ldg(w2f + (k    ) * 8 + aaB), acc2);
                acc2 = fmaf(h4.y, __ldg(w2f + (k + 1) * 8 + aaB), acc2);
                acc2 = fmaf(h4.z, __ldg(w2f + (k + 2) * 8 + aaB), acc2);
                acc2 = fmaf(h4.w, __ldg(w2f + (k + 3) * 8 + aaB), acc2);
            }
            float wf = fabsf(acc2) + 1e-10f;
            float adv = wf * (qv_pre - mq_pre);
            float asum = adv;
            asum += __shfl_xor_sync(0xffffffffu, asum, 1);
            asum += __shfl_xor_sync(0xffffffffu, asum, 2);
            asum += __shfl_xor_sync(0xffffffffu, asum, 4);
            sA[rB * 12 + aaB] = adv;
            if (aaB == 0) sA[rB * 12 + 8] = asum;
        }
        __syncwarp();                 // sh1 fully consumed before C tail overwrites swd

        // ---- C tail: store w_dvd ----
        const int hh = l >> 3, dd = 4 * (l & 7);
        #pragma unroll
        for (int r = 0; r < 4; r++) {
            float2 x0 = up2(cA[r][0]), x1 = up2(cA[r][1]);
            *(float4*)(swd + r * 148 + hh * 36 + dd) = make_float4(x0.x, x0.y, x1.x, x1.y);
        }
        __syncwarp();
    }

    // attA coefficients for this lane (reused for all 4 rows)
    const int hE = l >> 3, dE = l & 7;
    float4 a1 = __ldg((const float4*)(attA + hE * 64 + 4 * dE));
    float4 a2 = __ldg((const float4*)(attA + hE * 64 + 32 + 4 * dE));

    ull acc0[4][4], acc1[4][4];

    // ---------------- Pass 0: rows 0,1 ------------------------------------
    CP_WAIT0();                      // H01 landed
    __syncwarp();
    D_LOOP(acc0, acc1);
    phaseE(acc0, swd, sA, a1, a2, l, out, base, vv[0]);
    __syncwarp();                    // all lanes past D-loop sT reads
    STAGE_H_ASYNC(rr[2], rr[3]);     // H23 flies under phaseE(row1)
    phaseE(acc1, swd + 148, sA + 12, a1, a2, l, out, base + 1, vv[1]);

    // ---------------- Pass 1: rows 2,3 ------------------------------------
    CP_WAIT0();
    __syncwarp();
    D_LOOP(acc0, acc1);
    phaseE(acc0, swd + 2 * 148, sA + 2 * 12, a1, a2, l, out, base + 2, vv[2]);
    phaseE(acc1, swd + 3 * 148, sA + 3 * 12, a1, a2, l, out, base + 3, vv[3]);
}

extern "C" void kernel_launch(void* const* d_in, const int* in_sizes, int n_in,
                              void* d_out, int out_size)
{
    const float* Qv   = (const float*)d_in[0];   // agent_qs
    const float* S    = (const float*)d_in[1];   // states
    const float* MQ   = (const float*)d_in[2];   // max_q_i
    const float* H    = (const float*)d_in[3];   // hidden_states
    const float* w1f  = (const float*)d_in[4];
    const float* b1f  = (const float*)d_in[5];
    const float* w2f  = (const float*)d_in[6];
    const float* b2f  = (const float*)d_in[7];
    // d_in[8..11] = w1v,b1v,w2v,b2v : cancel algebraically in adv_q, unused
    const float* Wg   = (const float*)d_in[12];
    const float* attA = (const float*)d_in[13];
    const float* Wd   = (const float*)d_in[14];
    const float* bd   = (const float*)d_in[15];

    int B = in_sizes[0] / 8;                      // bs*T rows
    int rowsPerBlock = NWARPS * 4;
    int grid = (B + rowsPerBlock - 1) / rowsPerBlock;
    size_t smem = (size_t)NWARPS * WARP_FLOATS * sizeof(float);

    dvd_kernel<<<grid, NWARPS * 32, smem>>>((float*)d_out, Qv, S, MQ, H,
                                            w1f, b1f, w2f, b2f, Wg, attA, Wd, bd, B);
}